// round 10
// baseline (speedup 1.0000x reference)
#include <cuda_runtime.h>
#include <math.h>

// Problem constants
#define BATCH   4
#define NNODES  325
#define BN      (BATCH * NNODES)   // 1300
#define IDIM    64
#define HDIM    128
#define G4H     (4 * HDIM)         // 512
#define MAXNB   96
#define LN_EPS  1e-5f

// ---------------- scratch (__device__ globals; no allocation) ----------------
__device__ float g_gates[BN * G4H];
__device__ float g_h_lstm[BN * HDIM];
__device__ float g_support[BN * HDIM];
__device__ float g_hgraph[BN * HDIM];
__device__ float g_s[BN * HDIM];
__device__ float g_t[BN * HDIM];
__device__ int   g_nbr[BN * MAXNB];
__device__ float g_nbrw[BN * MAXNB];
__device__ int   g_cnt[BN];
// transposed weights (coalesced GEMM access)
__device__ float g_Wih_t[IDIM * G4H];        // [64][512]
__device__ float g_Whh_t[HDIM * G4H];        // [128][512]
__device__ float g_Wst_t[HDIM * 2 * HDIM];   // [128][256]: col<128 Ws, col>=128 Wt
__device__ float g_comb_t[2 * HDIM * HDIM];  // [256][128]

__device__ __forceinline__ float sigm_fast(float x) {
    return __fdividef(1.0f, 1.0f + __expf(-x));
}
__device__ __forceinline__ float tanh_fast(float x) {
    float cx = fminf(fmaxf(x, -15.0f), 15.0f);
    float e = __expf(2.0f * cx);
    return __fdividef(e - 1.0f, e + 1.0f);
}

// ============================================================================
// K0: prep = weight transposes + adjacency neighbor-list build (one launch).
// ============================================================================
#define TW_TOTAL (IDIM*G4H + HDIM*G4H + HDIM*2*HDIM + 2*HDIM*HDIM)
#define NTB ((TW_TOTAL + 255) / 256)
__global__ void __launch_bounds__(256)
prep_kernel(const float* __restrict__ W_ih, const float* __restrict__ W_hh,
            const float* __restrict__ Ws_w, const float* __restrict__ Wt_w,
            const float* __restrict__ comb_w, const float* __restrict__ adj)
{
    if (blockIdx.x < NTB) {
        int idx = blockIdx.x * 256 + threadIdx.x;
        if (idx < IDIM * G4H) {                       // Wih_t [64][512]
            int k = idx >> 9, g = idx & 511;
            g_Wih_t[idx] = __ldg(W_ih + g * IDIM + k);
            return;
        }
        idx -= IDIM * G4H;
        if (idx < HDIM * G4H) {                       // Whh_t [128][512]
            int k = idx >> 9, g = idx & 511;
            g_Whh_t[idx] = __ldg(W_hh + g * HDIM + k);
            return;
        }
        idx -= HDIM * G4H;
        if (idx < HDIM * 2 * HDIM) {                  // Wst_t [128][256]
            int k = idx >> 8, o = idx & 255;
            g_Wst_t[idx] = (o < HDIM) ? __ldg(Ws_w + o * HDIM + k)
                                      : __ldg(Wt_w + (o - HDIM) * HDIM + k);
            return;
        }
        idx -= HDIM * 2 * HDIM;
        if (idx < 2 * HDIM * HDIM) {                  // comb_t [256][128]
            int k = idx >> 7, o = idx & 127;
            g_comb_t[idx] = __ldg(comb_w + o * 2 * HDIM + k);
        }
        return;
    }

    // ---- adjacency scan: 8 warps, one row per warp, ballot compaction ----
    const int lane = threadIdx.x & 31;
    const int wrp  = threadIdx.x >> 5;
    const int row  = (blockIdx.x - NTB) * 8 + wrp;
    if (row >= BN) return;
    const int b = row / NNODES;
    const int i = row % NNODES;
    const float* arow = adj + (size_t)b * NNODES * NNODES + (size_t)i * NNODES;

    int cnt = 0;
    const unsigned lt = (1u << lane) - 1u;
    for (int j0 = 0; j0 < NNODES; j0 += 32) {
        int j = j0 + lane;
        float a = (j < NNODES) ? __ldg(arow + j) : 0.0f;
        unsigned m = __ballot_sync(0xffffffffu, a != 0.0f);
        int pos = cnt + __popc(m & lt);
        if (a != 0.0f && pos < MAXNB) {
            g_nbr[row * MAXNB + pos]  = j;
            g_nbrw[row * MAXNB + pos] = a;
        }
        cnt += __popc(m);
    }
    if (lane == 0) g_cnt[row] = min(cnt, MAXNB);
}

// ============================================================================
// K1: LSTM gates GEMM.  Grid (163, 4), 128 thr, 8 nodes/block.
// ============================================================================
#define LNT 8
__global__ void __launch_bounds__(128)
lstm_gemm_kernel(const float* __restrict__ x, const float* __restrict__ h,
                 const float* __restrict__ b_ih, const float* __restrict__ b_hh)
{
    __shared__ __align__(16) float sx[LNT][IDIM];
    __shared__ __align__(16) float sh[LNT][HDIM];

    const int node0 = blockIdx.x * LNT;
    const int o = threadIdx.x;
    const int g = blockIdx.y * HDIM + o;

    for (int idx = o; idx < LNT * IDIM; idx += 128) {
        int m = idx >> 6, k = idx & 63;
        int node = node0 + m;
        sx[m][k] = (node < BN) ? x[node * IDIM + k] : 0.0f;
    }
    for (int idx = o; idx < LNT * HDIM; idx += 128) {
        int m = idx >> 7, k = idx & 127;
        int node = node0 + m;
        sh[m][k] = (node < BN) ? h[node * HDIM + k] : 0.0f;
    }
    __syncthreads();

    float acc[LNT];
    const float bb = __ldg(b_ih + g) + __ldg(b_hh + g);
#pragma unroll
    for (int m = 0; m < LNT; m++) acc[m] = bb;

#pragma unroll 4
    for (int k4 = 0; k4 < IDIM / 4; k4++) {
        int k = k4 * 4;
        float w0 = g_Wih_t[(k + 0) * G4H + g];
        float w1 = g_Wih_t[(k + 1) * G4H + g];
        float w2 = g_Wih_t[(k + 2) * G4H + g];
        float w3 = g_Wih_t[(k + 3) * G4H + g];
#pragma unroll
        for (int m = 0; m < LNT; m++) {
            float4 a = *((const float4*)&sx[m][k]);
            acc[m] += a.x * w0 + a.y * w1 + a.z * w2 + a.w * w3;
        }
    }
#pragma unroll 4
    for (int k4 = 0; k4 < HDIM / 4; k4++) {
        int k = k4 * 4;
        float w0 = g_Whh_t[(k + 0) * G4H + g];
        float w1 = g_Whh_t[(k + 1) * G4H + g];
        float w2 = g_Whh_t[(k + 2) * G4H + g];
        float w3 = g_Whh_t[(k + 3) * G4H + g];
#pragma unroll
        for (int m = 0; m < LNT; m++) {
            float4 a = *((const float4*)&sh[m][k]);
            acc[m] += a.x * w0 + a.y * w1 + a.z * w2 + a.w * w3;
        }
    }
#pragma unroll
    for (int m = 0; m < LNT; m++) {
        int node = node0 + m;
        if (node < BN) g_gates[node * G4H + g] = acc[m];
    }
}

// ============================================================================
// K2: LSTM activations + support GEMM (m=2).  650 blocks, 128 threads.
// ============================================================================
__global__ void __launch_bounds__(128)
act_support_kernel(const float* __restrict__ c, const float* __restrict__ gc_w,
                   float* __restrict__ c_out)
{
    __shared__ float shh[2][HDIM];
    const int node0 = blockIdx.x * 2;
    const int u = threadIdx.x;

#pragma unroll
    for (int m = 0; m < 2; m++) {
        int node = node0 + m;
        const float* gb = g_gates + node * G4H;
        float ig = sigm_fast(gb[u]);
        float fg = sigm_fast(gb[HDIM + u]);
        float gg = tanh_fast(gb[2 * HDIM + u]);
        float og = sigm_fast(gb[3 * HDIM + u]);
        float cc = fg * c[node * HDIM + u] + ig * gg;
        float hh = og * tanh_fast(cc);
        c_out[node * HDIM + u] = cc;
        g_h_lstm[node * HDIM + u] = hh;
        shh[m][u] = hh;
    }
    __syncthreads();

    const int o = u;
    float a0 = 0.f, a1 = 0.f;
#pragma unroll 4
    for (int k = 0; k < HDIM; k++) {
        float w = __ldg(gc_w + k * HDIM + o);
        a0 += shh[0][k] * w;
        a1 += shh[1][k] * w;
    }
    g_support[node0 * HDIM + o] = a0;
    g_support[(node0 + 1) * HDIM + o] = a1;
}

// ============================================================================
// K3: graph conv gather (split over 2 thread-halves) + fused s/t GEMM.
// Block-per-row: 1300 blocks, 256 threads.
// ============================================================================
__global__ void __launch_bounds__(256)
graphconv_st_kernel(const float* __restrict__ gc_b, const float* __restrict__ Ws_b,
                    const float* __restrict__ Wt_b)
{
    const int row = blockIdx.x;
    const int b = row / NNODES;
    const int tid = threadIdx.x;
    const int half = tid >> 7;
    const int u = tid & 127;

    __shared__ int   lst[MAXNB];
    __shared__ float wv[MAXNB];
    __shared__ float part[2][HDIM];
    __shared__ float hg[HDIM];

    const int cn = g_cnt[row];
    for (int t = tid; t < cn; t += 256) {
        lst[t] = g_nbr[row * MAXNB + t];
        wv[t]  = g_nbrw[row * MAXNB + t];
    }
    __syncthreads();

    // gather: two halves each take every other neighbor
    float acc = (half == 0) ? __ldg(gc_b + u) : 0.0f;
    const float* supb = g_support + (size_t)b * NNODES * HDIM;
    for (int t = half; t < cn; t += 2)
        acc += wv[t] * __ldg(supb + (size_t)lst[t] * HDIM + u);
    part[half][u] = acc;
    __syncthreads();

    if (tid < HDIM) {
        float hv = part[0][u] + part[1][u];
        hg[u] = hv;
        g_hgraph[row * HDIM + u] = hv;
    }
    __syncthreads();

    // s/t GEMM: 256 threads, one output column each over fused [128][256] W
    const int oo = tid;
    float a = (oo < HDIM) ? __ldg(Ws_b + oo) : __ldg(Wt_b + oo - HDIM);
#pragma unroll 8
    for (int k = 0; k < HDIM; k++)
        a += hg[k] * g_Wst_t[k * 2 * HDIM + oo];
    if (oo < HDIM) g_s[row * HDIM + oo] = a;
    else           g_t[row * HDIM + (oo - HDIM)] = a;
}

// ============================================================================
// K4: attention + softmax + context + LayerNorm + combine.
// Block-per-row: 1300 blocks, 256 threads = 8 warps.
// ============================================================================
__global__ void __launch_bounds__(256)
attn_comb_kernel(const float* __restrict__ v, const float* __restrict__ ln_g,
                 const float* __restrict__ ln_b, const float* __restrict__ comb_b,
                 float* __restrict__ out)
{
    const int row = blockIdx.x;
    const int b = row / NNODES;
    const int tid = threadIdx.x;
    const int lane = tid & 31;
    const int wrp = tid >> 5;
    const int half = tid >> 7;
    const int u = tid & 127;

    __shared__ float s_sh[HDIM];
    __shared__ float v_sh[HDIM];
    __shared__ float hl_sh[HDIM];
    __shared__ float ha_sh[HDIM];
    __shared__ float part[2][HDIM];
    __shared__ float sc[MAXNB];
    __shared__ int   lst[MAXNB];
    __shared__ float red1[4], red2[4];

    if (tid < HDIM) {
        s_sh[tid]  = g_s[row * HDIM + tid];
        v_sh[tid]  = __ldg(v + tid);
        hl_sh[tid] = g_h_lstm[row * HDIM + tid];
    }
    const int cn = g_cnt[row];
    for (int t = tid; t < cn; t += 256) lst[t] = g_nbr[row * MAXNB + t];
    __syncthreads();

    // scores: 8 warps t-strided; lanes over features
    const float* tb = g_t + (size_t)b * NNODES * HDIM;
    for (int t = wrp; t < cn; t += 8) {
        const float* tj = tb + (size_t)lst[t] * HDIM;
        float p = 0.0f;
#pragma unroll
        for (int q = 0; q < 4; q++) {
            int uu = lane + q * 32;
            p += tanh_fast(s_sh[uu] + __ldg(tj + uu)) * v_sh[uu];
        }
#pragma unroll
        for (int off = 16; off > 0; off >>= 1)
            p += __shfl_xor_sync(0xffffffffu, p, off);
        if (lane == 0) sc[t] = p;
    }
    __syncthreads();

    // softmax (warp 0)
    if (wrp == 0) {
        float mx = -1e30f;
        for (int t = lane; t < cn; t += 32) mx = fmaxf(mx, sc[t]);
#pragma unroll
        for (int off = 16; off > 0; off >>= 1)
            mx = fmaxf(mx, __shfl_xor_sync(0xffffffffu, mx, off));
        float sm = 0.0f;
        for (int t = lane; t < cn; t += 32) {
            float e = __expf(sc[t] - mx);
            sc[t] = e;
            sm += e;
        }
#pragma unroll
        for (int off = 16; off > 0; off >>= 1)
            sm += __shfl_xor_sync(0xffffffffu, sm, off);
        float inv = __fdividef(1.0f, sm);
        for (int t = lane; t < cn; t += 32) sc[t] *= inv;
    }
    __syncthreads();

    // context: split neighbors across the two thread-halves
    float cacc = 0.0f;
    const float* hgb = g_hgraph + (size_t)b * NNODES * HDIM;
    for (int t = half; t < cn; t += 2)
        cacc += sc[t] * __ldg(hgb + (size_t)lst[t] * HDIM + u);
    part[half][u] = cacc;
    __syncthreads();

    // LayerNorm on threads < 128 (warps 0..3)
    if (tid < HDIM) {
        float acc = part[0][u] + part[1][u];
        float s1 = acc, s2 = acc * acc;
#pragma unroll
        for (int off = 16; off > 0; off >>= 1) {
            s1 += __shfl_xor_sync(0xffffffffu, s1, off);
            s2 += __shfl_xor_sync(0xffffffffu, s2, off);
        }
        if (lane == 0) { red1[wrp] = s1; red2[wrp] = s2; }
        part[0][u] = acc;     // stash context value
    }
    __syncthreads();
    if (tid < HDIM) {
        float acc = part[0][u];
        float tot1 = red1[0] + red1[1] + red1[2] + red1[3];
        float tot2 = red2[0] + red2[1] + red2[2] + red2[3];
        float mu = tot1 * (1.0f / HDIM);
        float var = tot2 * (1.0f / HDIM) - mu * mu;
        ha_sh[u] = __ldg(ln_g + u) * (acc - mu) * rsqrtf(var + LN_EPS) + __ldg(ln_b + u);
    }
    __syncthreads();

    // combine: split k across thread-halves (half0: hl, half1: ha)
    const int o = u;
    float ca = (half == 0) ? __ldg(comb_b + o) : 0.0f;
    const float* src = (half == 0) ? hl_sh : ha_sh;
    const float* wbase = g_comb_t + half * HDIM * HDIM;
#pragma unroll 8
    for (int k = 0; k < HDIM; k++)
        ca += src[k] * wbase[k * HDIM + o];
    part[half][o] = ca;
    __syncthreads();
    if (tid < HDIM)
        out[row * HDIM + o] = part[0][o] + part[1][o];
}

// ============================================================================
extern "C" void kernel_launch(void* const* d_in, const int* in_sizes, int n_in,
                              void* d_out, int out_size)
{
    const float* x      = (const float*)d_in[0];
    const float* adj    = (const float*)d_in[1];
    const float* h      = (const float*)d_in[2];
    const float* c      = (const float*)d_in[3];
    const float* b_ih   = (const float*)d_in[6];
    const float* b_hh   = (const float*)d_in[7];
    const float* gc_w   = (const float*)d_in[8];
    const float* gc_b   = (const float*)d_in[9];
    const float* Ws_b   = (const float*)d_in[11];
    const float* Wt_b   = (const float*)d_in[13];
    const float* v      = (const float*)d_in[14];
    const float* ln_g   = (const float*)d_in[15];
    const float* ln_b   = (const float*)d_in[16];
    const float* comb_b = (const float*)d_in[18];

    float* out = (float*)d_out;              // h_new, then c_lstm
    float* c_out = out + (size_t)BN * HDIM;

    const int scan_blocks = (BN + 7) / 8;    // 163
    prep_kernel<<<NTB + scan_blocks, 256>>>((const float*)d_in[4], (const float*)d_in[5],
                                            (const float*)d_in[10], (const float*)d_in[12],
                                            (const float*)d_in[17], adj);
    dim3 lstm_grid((BN + LNT - 1) / LNT, 4);          // 163 x 4
    lstm_gemm_kernel<<<lstm_grid, 128>>>(x, h, b_ih, b_hh);
    act_support_kernel<<<BN / 2, 128>>>(c, gc_w, c_out);          // 650
    graphconv_st_kernel<<<BN, 256>>>(gc_b, Ws_b, Wt_b);           // 1300
    attn_comb_kernel<<<BN, 256>>>(v, ln_g, ln_b, comb_b, out);    // 1300
}